// round 3
// baseline (speedup 1.0000x reference)
#include <cuda_runtime.h>
#include <math.h>

#define TPB 256
#define MAX_BLOCKS 2048
#define ANGW 0.1f
#define RAD2DEG 57.29577951308232f
#define PI_F 3.14159265358979f

__device__ float g_ptr_[MAX_BLOCKS];
__device__ float g_pang[MAX_BLOCKS];
__device__ unsigned int g_count = 0;

// Fast acos: Abramowitz-Stegun 4.4.45, max abs err ~6.7e-5 rad.
__device__ __forceinline__ float fast_acos(float x)
{
    float ax = fabsf(x);
    float p = fmaf(ax, -0.0187293f, 0.0742610f);
    p = fmaf(p, ax, -0.2121144f);
    p = fmaf(p, ax, 1.5707288f);
    float s = fmaxf(1.0f - ax, 1e-30f);
    float r = s * rsqrtf(s) * p;           // sqrt(s)*p
    return (x >= 0.f) ? r : PI_F - r;
}

// Eigenvector of symmetric A for eigenvalue lam: largest cross product of rows of (A - lam I).
__device__ __forceinline__ void eigvec3(
    float a00, float a01, float a02, float a11, float a12, float a22,
    float lam, float v[3])
{
    float r0x = a00 - lam, r0y = a01,       r0z = a02;
    float r1x = a01,       r1y = a11 - lam, r1z = a12;
    float r2x = a02,       r2y = a12,       r2z = a22 - lam;

    float c0x = r0y*r1z - r0z*r1y, c0y = r0z*r1x - r0x*r1z, c0z = r0x*r1y - r0y*r1x;
    float c1x = r0y*r2z - r0z*r2y, c1y = r0z*r2x - r0x*r2z, c1z = r0x*r2y - r0y*r2x;
    float c2x = r1y*r2z - r1z*r2y, c2y = r1z*r2x - r1x*r2z, c2z = r1x*r2y - r1y*r2x;

    float n0 = fmaf(c0x,c0x, fmaf(c0y,c0y, c0z*c0z));
    float n1 = fmaf(c1x,c1x, fmaf(c1y,c1y, c1z*c1z));
    float n2 = fmaf(c2x,c2x, fmaf(c2y,c2y, c2z*c2z));

    // branch-free max-pick
    float bx = (n1 > n0) ? c1x : c0x;
    float by = (n1 > n0) ? c1y : c0y;
    float bz = (n1 > n0) ? c1z : c0z;
    float bn = fmaxf(n0, n1);
    bx = (n2 > bn) ? c2x : bx;
    by = (n2 > bn) ? c2y : by;
    bz = (n2 > bn) ? c2z : bz;
    bn = fmaxf(bn, n2);

    float inv = rsqrtf(fmaxf(bn, 1e-30f));
    v[0] = bx*inv; v[1] = by*inv; v[2] = bz*inv;
}

// Nearest rotation (special-orthogonal Procrustes) to 3x3 row-major M. Branch-free.
__device__ __forceinline__ void nearest_rotation(const float M[9], float R[9])
{
    // A = M^T M
    float a00 = fmaf(M[0],M[0], fmaf(M[3],M[3], M[6]*M[6]));
    float a11 = fmaf(M[1],M[1], fmaf(M[4],M[4], M[7]*M[7]));
    float a22 = fmaf(M[2],M[2], fmaf(M[5],M[5], M[8]*M[8]));
    float a01 = fmaf(M[0],M[1], fmaf(M[3],M[4], M[6]*M[7]));
    float a02 = fmaf(M[0],M[2], fmaf(M[3],M[5], M[6]*M[8]));
    float a12 = fmaf(M[1],M[2], fmaf(M[4],M[5], M[7]*M[8]));

    // Cardano eigenvalues (lam1 >= lam2 >= lam3)
    float q   = (a00 + a11 + a22) * (1.0f/3.0f);
    float b00 = a00 - q, b11 = a11 - q, b22 = a22 - q;
    float p2  = fmaf(b00,b00, fmaf(b11,b11, b22*b22))
              + 2.0f*fmaf(a01,a01, fmaf(a02,a02, a12*a12));
    float p2s = fmaxf(p2 * (1.0f/6.0f), 1e-30f);
    float ip  = rsqrtf(p2s);               // 1/p
    float p   = p2s * ip;                  // p
    float det = b00*fmaf(b11,b22, -a12*a12)
              - a01*fmaf(a01,b22, -a12*a02)
              + a02*fmaf(a01,a12, -b11*a02);
    float rr = 0.5f * det * ip * ip * ip;
    rr = fminf(1.0f, fmaxf(-1.0f, rr));
    float phi = fast_acos(rr) * (1.0f/3.0f);
    float s, c;
    __sincosf(phi, &s, &c);
    float lam1 = fmaf(2.0f*p, c, q);
    float lam3 = fmaf(p, -c - 1.7320508075688772f*s, q);
    float lam2 = 3.0f*q - lam1 - lam3;

    float v1[3], v3[3];
    eigvec3(a00, a01, a02, a11, a12, a22, lam1, v1);
    eigvec3(a00, a01, a02, a11, a12, a22, lam3, v3);

    // v2 = v3 x v1 -> right-handed V
    float v2x = v3[1]*v1[2] - v3[2]*v1[1];
    float v2y = v3[2]*v1[0] - v3[0]*v1[2];
    float v2z = v3[0]*v1[1] - v3[1]*v1[0];

    // u_i = M v_i / sigma_i  (sigma_i = sqrt(lam_i))
    float is1 = rsqrtf(fmaxf(lam1, 1e-30f));
    float is2 = rsqrtf(fmaxf(lam2, 1e-30f));

    float u1x = fmaf(M[0],v1[0], fmaf(M[1],v1[1], M[2]*v1[2])) * is1;
    float u1y = fmaf(M[3],v1[0], fmaf(M[4],v1[1], M[5]*v1[2])) * is1;
    float u1z = fmaf(M[6],v1[0], fmaf(M[7],v1[1], M[8]*v1[2])) * is1;

    float u2x = fmaf(M[0],v2x, fmaf(M[1],v2y, M[2]*v2z)) * is2;
    float u2y = fmaf(M[3],v2x, fmaf(M[4],v2y, M[5]*v2z)) * is2;
    float u2z = fmaf(M[6],v2x, fmaf(M[7],v2y, M[8]*v2z)) * is2;

    // u3 = u1 x u2 (encodes the SVD det-correction)
    float u3x = u1y*u2z - u1z*u2y;
    float u3y = u1z*u2x - u1x*u2z;
    float u3z = u1x*u2y - u1y*u2x;

    // R = u1 v1^T + u2 v2^T + u3 v3^T
    R[0] = fmaf(u1x,v1[0], fmaf(u2x,v2x, u3x*v3[0]));
    R[1] = fmaf(u1x,v1[1], fmaf(u2x,v2y, u3x*v3[1]));
    R[2] = fmaf(u1x,v1[2], fmaf(u2x,v2z, u3x*v3[2]));
    R[3] = fmaf(u1y,v1[0], fmaf(u2y,v2x, u3y*v3[0]));
    R[4] = fmaf(u1y,v1[1], fmaf(u2y,v2y, u3y*v3[1]));
    R[5] = fmaf(u1y,v1[2], fmaf(u2y,v2z, u3y*v3[2]));
    R[6] = fmaf(u1z,v1[0], fmaf(u2z,v2x, u3z*v3[0]));
    R[7] = fmaf(u1z,v1[1], fmaf(u2z,v2y, u3z*v3[1]));
    R[8] = fmaf(u1z,v1[2], fmaf(u2z,v2z, u3z*v3[2]));
}

__global__ void __launch_bounds__(TPB, 6)
rotloss_kernel(const float* __restrict__ pred, const float* __restrict__ target,
               float* __restrict__ out, int B, float invB)
{
    __shared__ float sp[TPB*9];
    __shared__ float st_[TPB*9];

    float trs = 0.f, ang = 0.f;

    int ibase = blockIdx.x * TPB;          // first item of this block
    if (ibase < B) {
        int nitems = min(TPB, B - ibase);
        int nflt   = nitems * 9;
        long fbase = (long)ibase * 9;

        if ((nflt & 3) == 0 && nitems == TPB) {
            // fast path: aligned float4 bulk copy (2304 floats = 576 float4)
            const float4* p4 = (const float4*)(pred + fbase);
            const float4* t4 = (const float4*)(target + fbase);
            #pragma unroll
            for (int j = threadIdx.x; j < (TPB*9)/4; j += TPB) {
                ((float4*)sp)[j]  = p4[j];
                ((float4*)st_)[j] = t4[j];
            }
        } else {
            for (int j = threadIdx.x; j < nflt; j += TPB) {
                sp[j]  = pred[fbase + j];
                st_[j] = target[fbase + j];
            }
        }
        __syncthreads();

        if (threadIdx.x < nitems) {
            float P[9], T[9], Rp[9], Rt[9];
            #pragma unroll
            for (int k = 0; k < 9; k++) P[k] = sp[9*threadIdx.x + k];
            #pragma unroll
            for (int k = 0; k < 9; k++) T[k] = st_[9*threadIdx.x + k];

            nearest_rotation(P, Rp);
            nearest_rotation(T, Rt);

            float tr = 0.f;
            #pragma unroll
            for (int k = 0; k < 9; k++) tr = fmaf(Rp[k], Rt[k], tr);
            trs = tr;
            float ct = (tr - 1.0f) * 0.5f;
            ct = fminf(1.0f - 1e-7f, fmaxf(-1.0f + 1e-7f, ct));
            ang = fast_acos(ct) * RAD2DEG;
        }
    }

    // block reduction
    #pragma unroll
    for (int off = 16; off; off >>= 1) {
        trs += __shfl_down_sync(0xffffffffu, trs, off);
        ang += __shfl_down_sync(0xffffffffu, ang, off);
    }
    __shared__ float str[TPB/32], sang[TPB/32];
    int w = threadIdx.x >> 5, l = threadIdx.x & 31;
    if (l == 0) { str[w] = trs; sang[w] = ang; }
    __syncthreads();
    if (threadIdx.x == 0) {
        float t2 = 0.f, a2 = 0.f;
        #pragma unroll
        for (int j = 0; j < TPB/32; j++) { t2 += str[j]; a2 += sang[j]; }
        g_ptr_[blockIdx.x] = t2;
        g_pang[blockIdx.x] = a2;
    }

    // last-block finalize (self-resetting counter -> graph-replay safe)
    __threadfence();
    __shared__ bool isLast;
    if (threadIdx.x == 0) {
        unsigned int t = atomicAdd(&g_count, 1u);
        isLast = (t == gridDim.x - 1);
    }
    __syncthreads();
    if (!isLast) return;

    float t2 = 0.f, a2 = 0.f;
    for (int j = threadIdx.x; j < (int)gridDim.x; j += TPB) {
        t2 += g_ptr_[j];
        a2 += g_pang[j];
    }
    #pragma unroll
    for (int off = 16; off; off >>= 1) {
        t2 += __shfl_down_sync(0xffffffffu, t2, off);
        a2 += __shfl_down_sync(0xffffffffu, a2, off);
    }
    __shared__ float ftr[TPB/32], fang[TPB/32];
    if (l == 0) { ftr[w] = t2; fang[w] = a2; }
    __syncthreads();
    if (threadIdx.x == 0) {
        float tt = 0.f, aa = 0.f;
        #pragma unroll
        for (int j = 0; j < TPB/32; j++) { tt += ftr[j]; aa += fang[j]; }
        out[0] = fmaf(-2.0f * invB, tt, 6.0f) + ANGW * aa * invB;
        g_count = 0;   // reset for next graph replay
    }
}

extern "C" void kernel_launch(void* const* d_in, const int* in_sizes, int n_in,
                              void* d_out, int out_size)
{
    const float* pred   = (const float*)d_in[0];
    const float* target = (const float*)d_in[1];
    float* out = (float*)d_out;

    int B = in_sizes[0] / 9;
    int blocks = (B + TPB - 1) / TPB;
    if (blocks > MAX_BLOCKS) blocks = MAX_BLOCKS;   // B <= 524288 for this problem
    if (blocks < 1) blocks = 1;

    rotloss_kernel<<<blocks, TPB>>>(pred, target, out, B, 1.0f / (float)B);
}